// round 1
// baseline (speedup 1.0000x reference)
#include <cuda_runtime.h>
#include <math.h>

#define L    768
#define CS   384
#define CZ   128
#define H    12
#define D    32
#define PQK  4
#define PV   8
#define NQP  (H*PQK)      // 48 points
#define NVP  (H*PV)       // 96 points
#define OUTD 2208
#define LL   (L*L)

// ---------------- device scratch (static, no allocation) ----------------
__device__ float g_s   [L*CS];
__device__ float g_q   [L*CS];
__device__ float g_k   [L*CS];
__device__ float g_v   [L*CS];
__device__ float g_qp  [L*NQP*3];
__device__ float g_kp  [L*NQP*3];
__device__ float g_vp  [L*NVP*3];
__device__ float g_qg  [L*NQP*3];
__device__ float g_kg  [L*NQP*3];
__device__ float g_vg  [L*NVP*3];
__device__ float g_qn  [L*H];
__device__ float g_kn  [L*H];
__device__ float g_attn[(size_t)H*LL];   // 28.3 MB
__device__ float g_optg[L*NVP*3];
__device__ float g_cat [L*OUTD];         // 6.8 MB

// ---------------- layernorm: one block per residue ----------------
__global__ void k_ln(const float* __restrict__ x, const float* __restrict__ g,
                     const float* __restrict__ b) {
    int l = blockIdx.x, t = threadIdx.x;   // blockDim = 384
    __shared__ float red[12];
    __shared__ float s_mu, s_rs;
    float v = x[l*CS + t];
    float s = v;
    #pragma unroll
    for (int o = 16; o; o >>= 1) s += __shfl_xor_sync(0xffffffffu, s, o);
    if ((t & 31) == 0) red[t >> 5] = s;
    __syncthreads();
    if (t == 0) { float z = 0.f; for (int i = 0; i < 12; i++) z += red[i]; s_mu = z / CS; }
    __syncthreads();
    float c = v - s_mu;
    s = c * c;
    #pragma unroll
    for (int o = 16; o; o >>= 1) s += __shfl_xor_sync(0xffffffffu, s, o);
    if ((t & 31) == 0) red[t >> 5] = s;
    __syncthreads();
    if (t == 0) { float z = 0.f; for (int i = 0; i < 12; i++) z += red[i]; s_rs = rsqrtf(z / CS + 1e-5f); }
    __syncthreads();
    g_s[l*CS + t] = c * s_rs * g[t] + b[t];
}

// ---------------- projections: g_s [L,384] @ W [384,N] + bias ----------------
__global__ void k_proj(const float* __restrict__ W, const float* __restrict__ bias,
                       int which, int N) {
    float* C;
    switch (which) {
        case 0: C = g_q;  break;
        case 1: C = g_k;  break;
        case 2: C = g_v;  break;
        case 3: C = g_qp; break;
        case 4: C = g_kp; break;
        default: C = g_vp; break;
    }
    __shared__ float As[16][17], Bs[16][17];
    int tx = threadIdx.x, ty = threadIdx.y;
    int row = blockIdx.y * 16 + ty;
    int col = blockIdx.x * 16 + tx;
    float acc = bias ? bias[col] : 0.f;
    for (int k0 = 0; k0 < CS; k0 += 16) {
        As[ty][tx] = g_s[row*CS + k0 + tx];
        Bs[ty][tx] = W[(k0 + ty)*N + col];
        __syncthreads();
        #pragma unroll
        for (int kk = 0; kk < 16; kk++) acc += As[ty][kk] * Bs[kk][tx];
        __syncthreads();
    }
    C[row*N + col] = acc;
}

// ---------------- apply frames: global = R * local + t ----------------
__global__ void k_frames(const float* __restrict__ rots, const float* __restrict__ trans,
                         int which) {
    const float* src; float* dst; int npts;
    if (which == 0)      { src = g_qp; dst = g_qg; npts = NQP; }
    else if (which == 1) { src = g_kp; dst = g_kg; npts = NQP; }
    else                 { src = g_vp; dst = g_vg; npts = NVP; }
    int idx = blockIdx.x * blockDim.x + threadIdx.x;
    if (idx >= L * npts) return;
    int l = idx / npts, n = idx % npts;
    const float* R = rots + l*9;
    const float* p = src + (size_t)(l*npts + n)*3;
    float x = p[0], y = p[1], z = p[2];
    float* o = dst + (size_t)(l*npts + n)*3;
    o[0] = R[0]*x + R[1]*y + R[2]*z + trans[l*3 + 0];
    o[1] = R[3]*x + R[4]*y + R[5]*z + trans[l*3 + 1];
    o[2] = R[6]*x + R[7]*y + R[8]*z + trans[l*3 + 2];
}

// ---------------- squared norms of global q/k points per (l,h) ----------------
__global__ void k_norms() {
    int idx = blockIdx.x * blockDim.x + threadIdx.x;
    if (idx >= L*H) return;
    int l = idx / H, h = idx % H;
    float a = 0.f, b = 0.f;
    #pragma unroll
    for (int m = 0; m < PQK*3; m++) {
        float q = g_qg[l*(NQP*3) + h*(PQK*3) + m]; a += q*q;
        float k = g_kg[l*(NQP*3) + h*(PQK*3) + m]; b += k*k;
    }
    g_qn[idx] = a; g_kn[idx] = b;
}

// ---------------- pair bias: attn[h,i,j] = pair[i,j,:] . Wpb[:,h] ----------------
__global__ void k_bias(const float* __restrict__ pair, const float* __restrict__ Wpb) {
    __shared__ float w[CZ*H];   // 1536 floats
    for (int x = threadIdx.x; x < CZ*H; x += blockDim.x) w[x] = Wpb[x];
    __syncthreads();
    int n = blockIdx.x * blockDim.x + threadIdx.x;   // n = i*L + j
    float acc[H];
    #pragma unroll
    for (int h = 0; h < H; h++) acc[h] = 0.f;
    const float4* p4 = (const float4*)(pair + (size_t)n * CZ);
    #pragma unroll 4
    for (int c4 = 0; c4 < CZ/4; c4++) {
        float4 v = p4[c4];
        int c = c4 * 4;
        #pragma unroll
        for (int h = 0; h < H; h++) {
            acc[h] += v.x * w[(c+0)*H + h];
            acc[h] += v.y * w[(c+1)*H + h];
            acc[h] += v.z * w[(c+2)*H + h];
            acc[h] += v.w * w[(c+3)*H + h];
        }
    }
    #pragma unroll
    for (int h = 0; h < H; h++) g_attn[(size_t)h*LL + n] = acc[h];
}

// ---------------- logits: += qk/sqrt(D) - 0.5*wc*dist ----------------
__global__ void k_logits(const float* __restrict__ hw) {
    int h  = blockIdx.z;
    int i0 = blockIdx.y * 16, j0 = blockIdx.x * 16;
    int tx = threadIdx.x, ty = threadIdx.y;
    __shared__ float qs[16][33], ks[16][33];
    __shared__ float qgs[16][12], kgs[16][12];
    __shared__ float qns[16], kns[16];
    int i = i0 + ty, j = j0 + ty;
    qs[ty][tx]      = g_q[i*CS + h*D + tx];
    qs[ty][tx + 16] = g_q[i*CS + h*D + tx + 16];
    ks[ty][tx]      = g_k[j*CS + h*D + tx];
    ks[ty][tx + 16] = g_k[j*CS + h*D + tx + 16];
    if (tx < 12) {
        qgs[ty][tx] = g_qg[i*(NQP*3) + h*12 + tx];
        kgs[ty][tx] = g_kg[j*(NQP*3) + h*12 + tx];
    }
    if (tx == 12) { qns[ty] = g_qn[i*H + h]; kns[ty] = g_kn[j*H + h]; }
    __syncthreads();
    float dot = 0.f;
    #pragma unroll
    for (int d = 0; d < D; d++) dot += qs[ty][d] * ks[tx][d];
    float pd = 0.f;
    #pragma unroll
    for (int m = 0; m < 12; m++) pd += qgs[ty][m] * kgs[tx][m];
    float wc = log1pf(expf(hw[h]));
    float dist = qns[ty] + kns[tx] - 2.f * pd;
    size_t idx = (size_t)h*LL + (size_t)(i0 + ty)*L + (j0 + tx);
    g_attn[idx] += dot * 0.17677669529663687f - 0.5f * wc * dist;
}

// ---------------- softmax over j (row length 768) ----------------
__global__ void k_softmax() {
    int row = blockIdx.x;             // h*L + i
    float* a = g_attn + (size_t)row * L;
    int t = threadIdx.x;              // 256
    __shared__ float red[8];
    __shared__ float s_m, s_s;
    float v0 = a[t], v1 = a[t + 256], v2 = a[t + 512];
    float m = fmaxf(v0, fmaxf(v1, v2));
    #pragma unroll
    for (int o = 16; o; o >>= 1) m = fmaxf(m, __shfl_xor_sync(0xffffffffu, m, o));
    if ((t & 31) == 0) red[t >> 5] = m;
    __syncthreads();
    if (t == 0) { float z = red[0]; for (int i = 1; i < 8; i++) z = fmaxf(z, red[i]); s_m = z; }
    __syncthreads();
    float e0 = __expf(v0 - s_m), e1 = __expf(v1 - s_m), e2 = __expf(v2 - s_m);
    float s = e0 + e1 + e2;
    #pragma unroll
    for (int o = 16; o; o >>= 1) s += __shfl_xor_sync(0xffffffffu, s, o);
    if ((t & 31) == 0) red[t >> 5] = s;
    __syncthreads();
    if (t == 0) { float z = 0.f; for (int i = 0; i < 8; i++) z += red[i]; s_s = 1.f / z; }
    __syncthreads();
    a[t]       = e0 * s_s;
    a[t + 256] = e1 * s_s;
    a[t + 512] = e2 * s_s;
}

// ---------------- out_scalar: attn[h] @ v[:,h,:] -> cat[:,0:384] ----------------
__global__ void k_av() {
    int h = blockIdx.y, i0 = blockIdx.x * 32;
    int tx = threadIdx.x, ty = threadIdx.y;   // (32,8)
    __shared__ float as[32][33], vs[32][33];
    float acc[4] = {0.f, 0.f, 0.f, 0.f};
    for (int j0 = 0; j0 < L; j0 += 32) {
        #pragma unroll
        for (int r = 0; r < 4; r++) {
            int ii = ty + 8*r;
            as[ii][tx] = g_attn[(size_t)h*LL + (size_t)(i0 + ii)*L + j0 + tx];
            vs[ii][tx] = g_v[(j0 + ii)*CS + h*D + tx];
        }
        __syncthreads();
        #pragma unroll
        for (int jj = 0; jj < 32; jj++) {
            float vv = vs[jj][tx];
            #pragma unroll
            for (int r = 0; r < 4; r++) acc[r] += as[ty + 8*r][jj] * vv;
        }
        __syncthreads();
    }
    #pragma unroll
    for (int r = 0; r < 4; r++)
        g_cat[(size_t)(i0 + ty + 8*r)*OUTD + h*D + tx] = acc[r];
}

// ---------------- out_pts(global): attn[h] @ v_g[:,h,:,:] ----------------
__global__ void k_avpts() {
    int h = blockIdx.y, i0 = blockIdx.x * 32;
    int tx = threadIdx.x, ty = threadIdx.y;   // (32,8); tx<24 used for compute
    __shared__ float as[32][33], vs[32][25];
    float acc[4] = {0.f, 0.f, 0.f, 0.f};
    for (int j0 = 0; j0 < L; j0 += 32) {
        #pragma unroll
        for (int r = 0; r < 4; r++) {
            int ii = ty + 8*r;
            as[ii][tx] = g_attn[(size_t)h*LL + (size_t)(i0 + ii)*L + j0 + tx];
            if (tx < 24) vs[ii][tx] = g_vg[(size_t)(j0 + ii)*(NVP*3) + h*24 + tx];
        }
        __syncthreads();
        if (tx < 24) {
            #pragma unroll
            for (int jj = 0; jj < 32; jj++) {
                float vv = vs[jj][tx];
                #pragma unroll
                for (int r = 0; r < 4; r++) acc[r] += as[ty + 8*r][jj] * vv;
            }
        }
        __syncthreads();
    }
    if (tx < 24) {
        #pragma unroll
        for (int r = 0; r < 4; r++)
            g_optg[(size_t)(i0 + ty + 8*r)*(NVP*3) + h*24 + tx] = acc[r];
    }
}

// ---------------- invert frames on output points -> cat[:,384:672] ----------------
__global__ void k_ptsl(const float* __restrict__ rots, const float* __restrict__ trans) {
    int idx = blockIdx.x * blockDim.x + threadIdx.x;
    if (idx >= L * NVP) return;
    int l = idx / NVP, n = idx % NVP;
    const float* R = rots + l*9;
    float x = g_optg[l*(NVP*3) + n*3 + 0] - trans[l*3 + 0];
    float y = g_optg[l*(NVP*3) + n*3 + 1] - trans[l*3 + 1];
    float z = g_optg[l*(NVP*3) + n*3 + 2] - trans[l*3 + 2];
    // local_i = sum_j R[j,i] * f_j  (R^T)
    g_cat[(size_t)l*OUTD + CS + n*3 + 0] = R[0]*x + R[3]*y + R[6]*z;
    g_cat[(size_t)l*OUTD + CS + n*3 + 1] = R[1]*x + R[4]*y + R[7]*z;
    g_cat[(size_t)l*OUTD + CS + n*3 + 2] = R[2]*x + R[5]*y + R[8]*z;
}

// ---------------- out_pair: per-i GEMM attn_i[12,768] @ pair_i[768,128] ----------------
__global__ void k_opair(const float* __restrict__ pair) {
    int i = blockIdx.x;
    int t = threadIdx.x;   // 256
    __shared__ float as[H][L];   // 36 KB
    for (int x = t; x < H*L; x += 256) {
        int hh = x / L, jj = x % L;
        as[hh][jj] = g_attn[(size_t)hh*LL + (size_t)i*L + jj];
    }
    __syncthreads();
    int c = t & 127, half = t >> 7, h0 = half * 6;
    float acc[6] = {0.f, 0.f, 0.f, 0.f, 0.f, 0.f};
    const float* pr = pair + (size_t)i * L * CZ + c;
    for (int j = 0; j < L; j++) {
        float pv = pr[(size_t)j * CZ];
        #pragma unroll
        for (int hh = 0; hh < 6; hh++) acc[hh] += as[h0 + hh][j] * pv;
    }
    #pragma unroll
    for (int hh = 0; hh < 6; hh++)
        g_cat[(size_t)i*OUTD + CS + NVP*3 + (h0 + hh)*CZ + c] = acc[hh];
}

// ---------------- final: cat[768,2208] @ Wo[2208,384] + bo ----------------
__global__ void k_final(const float* __restrict__ Wo, const float* __restrict__ bo,
                        float* __restrict__ out) {
    __shared__ float As[16][17], Bs[16][17];
    int tx = threadIdx.x, ty = threadIdx.y;
    int row = blockIdx.y * 16 + ty;
    int col = blockIdx.x * 16 + tx;
    float acc = bo[col];
    for (int k0 = 0; k0 < OUTD; k0 += 16) {
        As[ty][tx] = g_cat[(size_t)row*OUTD + k0 + tx];
        Bs[ty][tx] = Wo[(size_t)(k0 + ty)*CS + col];
        __syncthreads();
        #pragma unroll
        for (int kk = 0; kk < 16; kk++) acc += As[ty][kk] * Bs[kk][tx];
        __syncthreads();
    }
    out[row*CS + col] = acc;
}

// ---------------- launch ----------------
extern "C" void kernel_launch(void* const* d_in, const int* in_sizes, int n_in,
                              void* d_out, int out_size) {
    const float* single = (const float*)d_in[0];
    const float* pair   = (const float*)d_in[1];
    const float* rots   = (const float*)d_in[2];
    const float* trans  = (const float*)d_in[3];
    const float* ln_g   = (const float*)d_in[4];
    const float* ln_b   = (const float*)d_in[5];
    const float* Wq     = (const float*)d_in[6];
    const float* Wk     = (const float*)d_in[7];
    const float* Wv     = (const float*)d_in[8];
    const float* Wqp    = (const float*)d_in[9];
    const float* bqp    = (const float*)d_in[10];
    const float* Wkp    = (const float*)d_in[11];
    const float* bkp    = (const float*)d_in[12];
    const float* Wvp    = (const float*)d_in[13];
    const float* bvp    = (const float*)d_in[14];
    const float* Wpb    = (const float*)d_in[15];
    const float* hw     = (const float*)d_in[16];
    const float* Wo     = (const float*)d_in[17];
    const float* bo     = (const float*)d_in[18];
    float* out = (float*)d_out;

    dim3 b16(16, 16);

    k_ln<<<L, CS>>>(single, ln_g, ln_b);

    k_proj<<<dim3(CS/16,        L/16), b16>>>(Wq,  nullptr, 0, CS);
    k_proj<<<dim3(CS/16,        L/16), b16>>>(Wk,  nullptr, 1, CS);
    k_proj<<<dim3(CS/16,        L/16), b16>>>(Wv,  nullptr, 2, CS);
    k_proj<<<dim3((NQP*3)/16,   L/16), b16>>>(Wqp, bqp,     3, NQP*3);
    k_proj<<<dim3((NQP*3)/16,   L/16), b16>>>(Wkp, bkp,     4, NQP*3);
    k_proj<<<dim3((NVP*3)/16,   L/16), b16>>>(Wvp, bvp,     5, NVP*3);

    k_frames<<<(L*NQP + 255)/256, 256>>>(rots, trans, 0);
    k_frames<<<(L*NQP + 255)/256, 256>>>(rots, trans, 1);
    k_frames<<<(L*NVP + 255)/256, 256>>>(rots, trans, 2);
    k_norms<<<(L*H + 255)/256, 256>>>();

    k_bias<<<LL/256, 256>>>(pair, Wpb);
    k_logits<<<dim3(L/16, L/16, H), b16>>>(hw);
    k_softmax<<<H*L, 256>>>();

    k_av<<<dim3(L/32, H), dim3(32, 8)>>>();
    k_avpts<<<dim3(L/32, H), dim3(32, 8)>>>();
    k_ptsl<<<(L*NVP + 255)/256, 256>>>(rots, trans);
    k_opair<<<L, 256>>>(pair);

    k_final<<<dim3(CS/16, L/16), b16>>>(Wo, bo, out);
}

// round 4
// speedup vs baseline: 1.2087x; 1.2087x over previous
#include <cuda_runtime.h>
#include <math.h>

#define L    768
#define CS   384
#define CZ   128
#define H    12
#define D    32
#define NQP  48
#define NVP  96
#define OUTD 2208
#define LL   (L*L)
#define KP   48
#define KSPLIT 6

// ---------------- device scratch ----------------
__device__ float g_s  [L*CS];
__device__ float g_q  [L*CS];
__device__ float g_k  [L*CS];
__device__ float g_v  [L*CS];
__device__ float g_qp [L*NQP*3];
__device__ float g_kp [L*NQP*3];
__device__ float g_vp [L*NVP*3];
__device__ float g_vg [L*NVP*3];
__device__ float g_qpk[L*H*KP];
__device__ float g_kpk[L*H*KP];
__device__ float g_attn[(size_t)H*LL];
__device__ float g_optg[L*NVP*3];
__device__ float g_cat [L*OUTD];
__device__ float g_fpart[KSPLIT][L*CS];

// ---------------- layernorm ----------------
__global__ void k_ln(const float* __restrict__ x, const float* __restrict__ g,
                     const float* __restrict__ b) {
    int l = blockIdx.x, t = threadIdx.x;   // blockDim = 384
    __shared__ float red[12];
    __shared__ float s_mu, s_rs;
    float v = x[l*CS + t];
    float s = v;
    #pragma unroll
    for (int o = 16; o; o >>= 1) s += __shfl_xor_sync(0xffffffffu, s, o);
    if ((t & 31) == 0) red[t >> 5] = s;
    __syncthreads();
    if (t == 0) { float z = 0.f; for (int i = 0; i < 12; i++) z += red[i]; s_mu = z / CS; }
    __syncthreads();
    float c = v - s_mu;
    s = c * c;
    #pragma unroll
    for (int o = 16; o; o >>= 1) s += __shfl_xor_sync(0xffffffffu, s, o);
    if ((t & 31) == 0) red[t >> 5] = s;
    __syncthreads();
    if (t == 0) { float z = 0.f; for (int i = 0; i < 12; i++) z += red[i]; s_rs = rsqrtf(z / CS + 1e-5f); }
    __syncthreads();
    g_s[l*CS + t] = c * s_rs * g[t] + b[t];
}

// ---------------- projections: register-tiled 64x64 GEMM ----------------
__global__ __launch_bounds__(256)
void k_proj(const float* __restrict__ W, const float* __restrict__ bias,
            int which, int N) {
    float* C;
    switch (which) {
        case 0: C = g_q;  break;
        case 1: C = g_k;  break;
        case 2: C = g_v;  break;
        case 3: C = g_qp; break;
        case 4: C = g_kp; break;
        default: C = g_vp; break;
    }
    __shared__ float As[16][68], Bs[16][68];
    int t = threadIdx.x;
    int tx = t & 15, ty = t >> 4;
    int m0 = blockIdx.y * 64, n0 = blockIdx.x * 64;
    float acc[4][4] = {};
    for (int k0 = 0; k0 < CS; k0 += 16) {
        {
            int row = t >> 2, kq = (t & 3) * 4;
            float4 v = *(const float4*)&g_s[(m0 + row)*CS + k0 + kq];
            As[kq+0][row] = v.x; As[kq+1][row] = v.y;
            As[kq+2][row] = v.z; As[kq+3][row] = v.w;
        }
        {
            int col = n0 + tx * 4;
            float4 v;
            if (col + 3 < N) {
                v = *(const float4*)&W[(size_t)(k0 + ty)*N + col];
            } else {
                v.x = (col     < N) ? W[(size_t)(k0+ty)*N + col    ] : 0.f;
                v.y = (col + 1 < N) ? W[(size_t)(k0+ty)*N + col + 1] : 0.f;
                v.z = (col + 2 < N) ? W[(size_t)(k0+ty)*N + col + 2] : 0.f;
                v.w = (col + 3 < N) ? W[(size_t)(k0+ty)*N + col + 3] : 0.f;
            }
            *(float4*)&Bs[ty][tx*4] = v;
        }
        __syncthreads();
        #pragma unroll
        for (int k = 0; k < 16; k++) {
            float4 a = *(const float4*)&As[k][ty*4];
            float4 b = *(const float4*)&Bs[k][tx*4];
            acc[0][0] += a.x*b.x; acc[0][1] += a.x*b.y; acc[0][2] += a.x*b.z; acc[0][3] += a.x*b.w;
            acc[1][0] += a.y*b.x; acc[1][1] += a.y*b.y; acc[1][2] += a.y*b.z; acc[1][3] += a.y*b.w;
            acc[2][0] += a.z*b.x; acc[2][1] += a.z*b.y; acc[2][2] += a.z*b.z; acc[2][3] += a.z*b.w;
            acc[3][0] += a.w*b.x; acc[3][1] += a.w*b.y; acc[3][2] += a.w*b.z; acc[3][3] += a.w*b.w;
        }
        __syncthreads();
    }
    #pragma unroll
    for (int mi = 0; mi < 4; mi++) {
        int row = m0 + ty*4 + mi;
        #pragma unroll
        for (int ni = 0; ni < 4; ni++) {
            int col = n0 + tx*4 + ni;
            if (col < N) C[(size_t)row*N + col] = acc[mi][ni] + (bias ? bias[col] : 0.f);
        }
    }
}

// ---------------- frames for V points only ----------------
__global__ void k_framesV(const float* __restrict__ rots, const float* __restrict__ trans) {
    int idx = blockIdx.x * blockDim.x + threadIdx.x;
    if (idx >= L * NVP) return;
    int l = idx / NVP;
    const float* R = rots + l*9;
    const float* p = g_vp + (size_t)idx*3;
    float x = p[0], y = p[1], z = p[2];
    float* o = g_vg + (size_t)idx*3;
    o[0] = R[0]*x + R[1]*y + R[2]*z + trans[l*3 + 0];
    o[1] = R[3]*x + R[4]*y + R[5]*z + trans[l*3 + 1];
    o[2] = R[6]*x + R[7]*y + R[8]*z + trans[l*3 + 2];
}

// ---------------- pack q/k into 48-dim logit vectors ----------------
__global__ void k_pack(const float* __restrict__ rots, const float* __restrict__ trans,
                       const float* __restrict__ hw) {
    int idx = blockIdx.x * blockDim.x + threadIdx.x;
    if (idx >= L*H) return;
    int l = idx / H, h = idx % H;
    float R[9];
    #pragma unroll
    for (int i = 0; i < 9; i++) R[i] = rots[l*9 + i];
    float t0 = trans[l*3 + 0], t1 = trans[l*3 + 1], t2 = trans[l*3 + 2];
    float wc = log1pf(__expf(hw[h]));
    const float sc = 0.17677669529663687f;
    float* qo = g_qpk + (size_t)idx*KP;
    float* ko = g_kpk + (size_t)idx*KP;
    #pragma unroll
    for (int d = 0; d < D; d++) {
        qo[d] = g_q[l*CS + h*D + d] * sc;
        ko[d] = g_k[l*CS + h*D + d];
    }
    float qn = 0.f, kn = 0.f;
    #pragma unroll
    for (int p = 0; p < 4; p++) {
        const float* qp = &g_qp[l*(NQP*3) + h*12 + p*3];
        float x = qp[0], y = qp[1], z = qp[2];
        float gx = R[0]*x + R[1]*y + R[2]*z + t0;
        float gy = R[3]*x + R[4]*y + R[5]*z + t1;
        float gz = R[6]*x + R[7]*y + R[8]*z + t2;
        qn += gx*gx + gy*gy + gz*gz;
        qo[32 + p*3 + 0] = wc*gx; qo[32 + p*3 + 1] = wc*gy; qo[32 + p*3 + 2] = wc*gz;
        const float* kp = &g_kp[l*(NQP*3) + h*12 + p*3];
        x = kp[0]; y = kp[1]; z = kp[2];
        gx = R[0]*x + R[1]*y + R[2]*z + t0;
        gy = R[3]*x + R[4]*y + R[5]*z + t1;
        gz = R[6]*x + R[7]*y + R[8]*z + t2;
        kn += gx*gx + gy*gy + gz*gz;
        ko[32 + p*3 + 0] = gx; ko[32 + p*3 + 1] = gy; ko[32 + p*3 + 2] = gz;
    }
    qo[44] = -0.5f*wc*qn; qo[45] = 1.f; qo[46] = 0.f; qo[47] = 0.f;
    ko[44] = 1.f; ko[45] = -0.5f*wc*kn; ko[46] = 0.f; ko[47] = 0.f;
}

// ---------------- logits GEMM: [64x48]@[48x64] per (h, tile) ----------------
__global__ __launch_bounds__(256)
void k_logits() {
    int h = blockIdx.z;
    int i0 = blockIdx.y * 64, j0 = blockIdx.x * 64;
    __shared__ float As[KP][68], Bs[KP][68];
    int t = threadIdx.x, tx = t & 15, ty = t >> 4;
    {
        int row = t >> 2, kq = (t & 3) * 4;
        #pragma unroll
        for (int kk = 0; kk < KP; kk += 16) {
            float4 a = *(const float4*)&g_qpk[((size_t)(i0 + row)*H + h)*KP + kk + kq];
            As[kk+kq+0][row] = a.x; As[kk+kq+1][row] = a.y;
            As[kk+kq+2][row] = a.z; As[kk+kq+3][row] = a.w;
            float4 b = *(const float4*)&g_kpk[((size_t)(j0 + row)*H + h)*KP + kk + kq];
            Bs[kk+kq+0][row] = b.x; Bs[kk+kq+1][row] = b.y;
            Bs[kk+kq+2][row] = b.z; Bs[kk+kq+3][row] = b.w;
        }
    }
    __syncthreads();
    float acc[4][4] = {};
    #pragma unroll
    for (int k = 0; k < KP; k++) {
        float4 a = *(const float4*)&As[k][ty*4];
        float4 b = *(const float4*)&Bs[k][tx*4];
        acc[0][0] += a.x*b.x; acc[0][1] += a.x*b.y; acc[0][2] += a.x*b.z; acc[0][3] += a.x*b.w;
        acc[1][0] += a.y*b.x; acc[1][1] += a.y*b.y; acc[1][2] += a.y*b.z; acc[1][3] += a.y*b.w;
        acc[2][0] += a.z*b.x; acc[2][1] += a.z*b.y; acc[2][2] += a.z*b.z; acc[2][3] += a.z*b.w;
        acc[3][0] += a.w*b.x; acc[3][1] += a.w*b.y; acc[3][2] += a.w*b.z; acc[3][3] += a.w*b.w;
    }
    #pragma unroll
    for (int mi = 0; mi < 4; mi++) {
        float4 v = make_float4(acc[mi][0], acc[mi][1], acc[mi][2], acc[mi][3]);
        *(float4*)&g_attn[(size_t)h*LL + (size_t)(i0 + ty*4 + mi)*L + j0 + tx*4] = v;
    }
}

// ---------------- fused pair-bias + logit-add + softmax: block = one i ----------------
#define CT 8
__global__ __launch_bounds__(128)
void k_biassm(const float* __restrict__ pair, const float* __restrict__ Wpb) {
    int i = blockIdx.x, t = threadIdx.x;
    __shared__ float pj[CT][768];
    __shared__ float wsh[CZ*H];
    __shared__ float red[H][128];
    __shared__ float sred[H];
    for (int x = t; x < CZ*H; x += 128) wsh[x] = Wpb[x];
    float acc[6][12] = {};
    const float* prow = pair + (size_t)i * L * CZ;
    int c4 = (t & 1) * 4, jb = t >> 1;
    for (int c0 = 0; c0 < CZ; c0 += CT) {
        __syncthreads();
        #pragma unroll
        for (int pass = 0; pass < 12; pass++) {
            int j = jb + pass * 64;
            float4 v = *(const float4*)&prow[(size_t)j*CZ + c0 + c4];
            pj[c4+0][j] = v.x; pj[c4+1][j] = v.y; pj[c4+2][j] = v.z; pj[c4+3][j] = v.w;
        }
        __syncthreads();
        for (int ck = 0; ck < CT; ck++) {
            int c = c0 + ck;
            float wv[12];
            #pragma unroll
            for (int h = 0; h < 12; h++) wv[h] = wsh[c*12 + h];
            #pragma unroll
            for (int r = 0; r < 6; r++) {
                float a = pj[ck][t + 128*r];
                #pragma unroll
                for (int h = 0; h < 12; h++) acc[r][h] += a * wv[h];
            }
        }
    }
    // add precomputed logits
    #pragma unroll
    for (int h = 0; h < 12; h++)
        #pragma unroll
        for (int r = 0; r < 6; r++)
            acc[r][h] += g_attn[(size_t)h*LL + (size_t)i*L + t + 128*r];
    // softmax over j (distributed across threads)
    #pragma unroll
    for (int h = 0; h < 12; h++) {
        float m = acc[0][h];
        #pragma unroll
        for (int r = 1; r < 6; r++) m = fmaxf(m, acc[r][h]);
        red[h][t] = m;
    }
    __syncthreads();
    int w = t >> 5, lane = t & 31;
    {
        #pragma unroll
        for (int hh = 0; hh < 3; hh++) {
            int h = w*3 + hh;
            float m = fmaxf(fmaxf(red[h][lane], red[h][lane+32]),
                            fmaxf(red[h][lane+64], red[h][lane+96]));
            #pragma unroll
            for (int o = 16; o; o >>= 1) m = fmaxf(m, __shfl_xor_sync(0xffffffffu, m, o));
            if (lane == 0) sred[h] = m;
        }
    }
    __syncthreads();
    float mh[12];
    #pragma unroll
    for (int h = 0; h < 12; h++) mh[h] = sred[h];
    __syncthreads();
    #pragma unroll
    for (int h = 0; h < 12; h++) {
        float s = 0.f;
        #pragma unroll
        for (int r = 0; r < 6; r++) {
            acc[r][h] = __expf(acc[r][h] - mh[h]);
            s += acc[r][h];
        }
        red[h][t] = s;
    }
    __syncthreads();
    {
        #pragma unroll
        for (int hh = 0; hh < 3; hh++) {
            int h = w*3 + hh;
            float s = red[h][lane] + red[h][lane+32] + red[h][lane+64] + red[h][lane+96];
            #pragma unroll
            for (int o = 16; o; o >>= 1) s += __shfl_xor_sync(0xffffffffu, s, o);
            if (lane == 0) sred[h] = s;
        }
    }
    __syncthreads();
    #pragma unroll
    for (int h = 0; h < 12; h++) {
        float inv = 1.f / sred[h];
        #pragma unroll
        for (int r = 0; r < 6; r++)
            g_attn[(size_t)h*LL + (size_t)i*L + t + 128*r] = acc[r][h] * inv;
    }
}

// ---------------- fused AV (scalar 32 + points 24 = 56 features) ----------------
__global__ __launch_bounds__(256)
void k_avf() {
    int h = blockIdx.y, i0 = blockIdx.x * 64;
    __shared__ float As[32][68];   // [j][i]
    __shared__ float Bs[32][64];   // [j][f], f>=56 zero
    int t = threadIdx.x, tx = t & 15, ty = t >> 4;
    float acc[4][4] = {};
    for (int j0 = 0; j0 < L; j0 += 32) {
        #pragma unroll
        for (int p = 0; p < 2; p++) {
            int ii = (t >> 3) + p*32;
            int j4 = (t & 7) * 4;
            float4 v = *(const float4*)&g_attn[(size_t)h*LL + (size_t)(i0 + ii)*L + j0 + j4];
            As[j4+0][ii] = v.x; As[j4+1][ii] = v.y; As[j4+2][ii] = v.z; As[j4+3][ii] = v.w;
        }
        for (int x = t; x < 32*64; x += 256) {
            int j = x >> 6, f = x & 63;
            float v = 0.f;
            if (f < 32)      v = g_v [(size_t)(j0 + j)*CS + h*D + f];
            else if (f < 56) v = g_vg[(size_t)(j0 + j)*(NVP*3) + h*24 + f - 32];
            Bs[j][f] = v;
        }
        __syncthreads();
        #pragma unroll
        for (int j = 0; j < 32; j++) {
            float4 a = *(const float4*)&As[j][ty*4];
            float4 b = *(const float4*)&Bs[j][tx*4];
            acc[0][0] += a.x*b.x; acc[0][1] += a.x*b.y; acc[0][2] += a.x*b.z; acc[0][3] += a.x*b.w;
            acc[1][0] += a.y*b.x; acc[1][1] += a.y*b.y; acc[1][2] += a.y*b.z; acc[1][3] += a.y*b.w;
            acc[2][0] += a.z*b.x; acc[2][1] += a.z*b.y; acc[2][2] += a.z*b.z; acc[2][3] += a.z*b.w;
            acc[3][0] += a.w*b.x; acc[3][1] += a.w*b.y; acc[3][2] += a.w*b.z; acc[3][3] += a.w*b.w;
        }
        __syncthreads();
    }
    #pragma unroll
    for (int mi = 0; mi < 4; mi++) {
        int ii = i0 + ty*4 + mi;
        #pragma unroll
        for (int ni = 0; ni < 4; ni++) {
            int f = tx*4 + ni;
            if (f < 32)      g_cat[(size_t)ii*OUTD + h*D + f] = acc[mi][ni];
            else if (f < 56) g_optg[(size_t)ii*(NVP*3) + h*24 + f - 32] = acc[mi][ni];
        }
    }
}

// ---------------- invert frames on output points ----------------
__global__ void k_ptsl(const float* __restrict__ rots, const float* __restrict__ trans) {
    int idx = blockIdx.x * blockDim.x + threadIdx.x;
    if (idx >= L * NVP) return;
    int l = idx / NVP, n = idx % NVP;
    const float* R = rots + l*9;
    float x = g_optg[(size_t)idx*3 + 0] - trans[l*3 + 0];
    float y = g_optg[(size_t)idx*3 + 1] - trans[l*3 + 1];
    float z = g_optg[(size_t)idx*3 + 2] - trans[l*3 + 2];
    g_cat[(size_t)l*OUTD + CS + n*3 + 0] = R[0]*x + R[3]*y + R[6]*z;
    g_cat[(size_t)l*OUTD + CS + n*3 + 1] = R[1]*x + R[4]*y + R[7]*z;
    g_cat[(size_t)l*OUTD + CS + n*3 + 2] = R[2]*x + R[5]*y + R[8]*z;
}

// ---------------- out_pair: block = one i; warp-wide float4 rows ----------------
__global__ __launch_bounds__(256)
void k_opair(const float* __restrict__ pair) {
    int i = blockIdx.x, t = threadIdx.x, w = t >> 5, lane = t & 31;
    __shared__ float asr[H*L];     // 36 KB; reused as reduce buffer
    for (int x = t; x < H*L; x += 256)
        asr[x] = g_attn[(size_t)(x / L)*LL + (size_t)i*L + (x % L)];
    __syncthreads();
    float4 acc[12];
    #pragma unroll
    for (int h = 0; h < 12; h++) acc[h] = make_float4(0.f, 0.f, 0.f, 0.f);
    const float4* pr = (const float4*)(pair + (size_t)i * L * CZ);
    int jend = w*96 + 96;
    for (int j = w*96; j < jend; j++) {
        float4 p = pr[(size_t)j*32 + lane];
        #pragma unroll
        for (int h = 0; h < 12; h++) {
            float a = asr[h*L + j];
            acc[h].x += a*p.x; acc[h].y += a*p.y; acc[h].z += a*p.z; acc[h].w += a*p.w;
        }
    }
    for (int half = 4; half >= 1; half >>= 1) {
        __syncthreads();
        if (w >= half && w < 2*half) {
            #pragma unroll
            for (int h = 0; h < 12; h++)
                *(float4*)&asr[(w - half)*1536 + h*128 + lane*4] = acc[h];
        }
        __syncthreads();
        if (w < half) {
            #pragma unroll
            for (int h = 0; h < 12; h++) {
                float4 v = *(const float4*)&asr[w*1536 + h*128 + lane*4];
                acc[h].x += v.x; acc[h].y += v.y; acc[h].z += v.z; acc[h].w += v.w;
            }
        }
    }
    if (w == 0) {
        #pragma unroll
        for (int h = 0; h < 12; h++)
            *(float4*)&g_cat[(size_t)i*OUTD + CS + NVP*3 + h*128 + lane*4] = acc[h];
    }
}

// ---------------- final GEMM, split-K partials ----------------
__global__ __launch_bounds__(256)
void k_fpart(const float* __restrict__ Wo) {
    int n0 = blockIdx.x * 64, m0 = blockIdx.y * 64, kz = blockIdx.z;
    __shared__ float As[16][68], Bs[16][68];
    int t = threadIdx.x, tx = t & 15, ty = t >> 4;
    float acc[4][4] = {};
    int kbeg = kz * (OUTD / KSPLIT), kend = kbeg + OUTD / KSPLIT;
    for (int k0 = kbeg; k0 < kend; k0 += 16) {
        {
            int row = t >> 2, kq = (t & 3) * 4;
            float4 v = *(const float4*)&g_cat[(size_t)(m0 + row)*OUTD + k0 + kq];
            As[kq+0][row] = v.x; As[kq+1][row] = v.y;
            As[kq+2][row] = v.z; As[kq+3][row] = v.w;
        }
        {
            float4 v = *(const float4*)&Wo[(size_t)(k0 + ty)*CS + n0 + tx*4];
            *(float4*)&Bs[ty][tx*4] = v;
        }
        __syncthreads();
        #pragma unroll
        for (int k = 0; k < 16; k++) {
            float4 a = *(const float4*)&As[k][ty*4];
            float4 b = *(const float4*)&Bs[k][tx*4];
            acc[0][0] += a.x*b.x; acc[0][1] += a.x*b.y; acc[0][2] += a.x*b.z; acc[0][3] += a.x*b.w;
            acc[1][0] += a.y*b.x; acc[1][1] += a.y*b.y; acc[1][2] += a.y*b.z; acc[1][3] += a.y*b.w;
            acc[2][0] += a.z*b.x; acc[2][1] += a.z*b.y; acc[2][2] += a.z*b.z; acc[2][3] += a.z*b.w;
            acc[3][0] += a.w*b.x; acc[3][1] += a.w*b.y; acc[3][2] += a.w*b.z; acc[3][3] += a.w*b.w;
        }
        __syncthreads();
    }
    #pragma unroll
    for (int mi = 0; mi < 4; mi++) {
        float4 v = make_float4(acc[mi][0], acc[mi][1], acc[mi][2], acc[mi][3]);
        *(float4*)&g_fpart[kz][(size_t)(m0 + ty*4 + mi)*CS + n0 + tx*4] = v;
    }
}

__global__ void k_fred(const float* __restrict__ bo, float* __restrict__ out) {
    int x = blockIdx.x * 256 + threadIdx.x;
    if (x >= L*CS) return;
    float s = bo[x % CS];
    #pragma unroll
    for (int p = 0; p < KSPLIT; p++) s += g_fpart[p][x];
    out[x] = s;
}

// ---------------- launch ----------------
extern "C" void kernel_launch(void* const* d_in, const int* in_sizes, int n_in,
                              void* d_out, int out_size) {
    const float* single = (const float*)d_in[0];
    const float* pair   = (const float*)d_in[1];
    const float* rots   = (const float*)d_in[2];
    const float* trans  = (const float*)d_in[3];
    const float* ln_g   = (const float*)d_in[4];
    const float* ln_b   = (const float*)d_in[5];
    const float* Wq     = (const float*)d_in[6];
    const float* Wk     = (const float*)d_in[7];
    const float* Wv     = (const float*)d_in[8];
    const float* Wqp    = (const float*)d_in[9];
    const float* bqp    = (const float*)d_in[10];
    const float* Wkp    = (const float*)d_in[11];
    const float* bkp    = (const float*)d_in[12];
    const float* Wvp    = (const float*)d_in[13];
    const float* bvp    = (const float*)d_in[14];
    const float* Wpb    = (const float*)d_in[15];
    const float* hw     = (const float*)d_in[16];
    const float* Wo     = (const float*)d_in[17];
    const float* bo     = (const float*)d_in[18];
    float* out = (float*)d_out;

    k_ln<<<L, CS>>>(single, ln_g, ln_b);

    k_proj<<<dim3(6,  12), 256>>>(Wq,  nullptr, 0, CS);
    k_proj<<<dim3(6,  12), 256>>>(Wk,  nullptr, 1, CS);
    k_proj<<<dim3(6,  12), 256>>>(Wv,  nullptr, 2, CS);
    k_proj<<<dim3(3,  12), 256>>>(Wqp, bqp,     3, NQP*3);
    k_proj<<<dim3(3,  12), 256>>>(Wkp, bkp,     4, NQP*3);
    k_proj<<<dim3(5,  12), 256>>>(Wvp, bvp,     5, NVP*3);

    k_framesV<<<(L*NVP + 255)/256, 256>>>(rots, trans);
    k_pack<<<(L*H + 255)/256, 256>>>(rots, trans, hw);

    k_logits<<<dim3(12, 12, H), 256>>>();
    k_biassm<<<L, 128>>>(pair, Wpb);

    k_avf<<<dim3(12, H), 256>>>();
    k_ptsl<<<(L*NVP + 255)/256, 256>>>(rots, trans);
    k_opair<<<L, 256>>>(pair);

    k_fpart<<<dim3(6, 12, KSPLIT), 256>>>(Wo);
    k_fred<<<(L*CS + 255)/256, 256>>>(bo, out);
}

// round 6
// speedup vs baseline: 2.0780x; 1.7192x over previous
#include <cuda_runtime.h>
#include <math.h>

#define L    768
#define CS   384
#define CZ   128
#define H    12
#define D    32
#define NQP  48
#define NVP  96
#define OUTD 2208
#define LL   (L*L)
#define KP   48
#define KSPLIT 6

// ---------------- device scratch ----------------
__device__ float g_s  [L*CS];
__device__ float g_q  [L*CS];
__device__ float g_k  [L*CS];
__device__ float g_v  [L*CS];
__device__ float g_qp [L*NQP*3];
__device__ float g_kp [L*NQP*3];
__device__ float g_vp [L*NVP*3];
__device__ float g_vg [L*NVP*3];
__device__ float g_qpk[L*H*KP];
__device__ float g_kpk[L*H*KP];
__device__ float g_attn[(size_t)H*LL];
__device__ float g_optg[L*NVP*3];
__device__ float g_cat [L*OUTD];
__device__ float g_fpart[KSPLIT][L*CS];

// ---------------- layernorm ----------------
__global__ void k_ln(const float* __restrict__ x, const float* __restrict__ g,
                     const float* __restrict__ b) {
    int l = blockIdx.x, t = threadIdx.x;   // blockDim = 384
    __shared__ float red[12];
    __shared__ float s_mu, s_rs;
    float v = x[l*CS + t];
    float s = v;
    #pragma unroll
    for (int o = 16; o; o >>= 1) s += __shfl_xor_sync(0xffffffffu, s, o);
    if ((t & 31) == 0) red[t >> 5] = s;
    __syncthreads();
    if (t == 0) { float z = 0.f; for (int i = 0; i < 12; i++) z += red[i]; s_mu = z / CS; }
    __syncthreads();
    float c = v - s_mu;
    s = c * c;
    #pragma unroll
    for (int o = 16; o; o >>= 1) s += __shfl_xor_sync(0xffffffffu, s, o);
    if ((t & 31) == 0) red[t >> 5] = s;
    __syncthreads();
    if (t == 0) { float z = 0.f; for (int i = 0; i < 12; i++) z += red[i]; s_rs = rsqrtf(z / CS + 1e-5f); }
    __syncthreads();
    g_s[l*CS + t] = c * s_rs * g[t] + b[t];
}

// ---------------- ALL projections in one launch, pipelined ----------------
// n-tiles: q:0-5, k:6-11, v:12-17, qp:18-20, kp:21-23, vp:24-28  (29 tiles)
__global__ __launch_bounds__(256)
void k_projall(const float* __restrict__ Wq, const float* __restrict__ Wk,
               const float* __restrict__ Wv,
               const float* __restrict__ Wqp, const float* __restrict__ bqp,
               const float* __restrict__ Wkp, const float* __restrict__ bkp,
               const float* __restrict__ Wvp, const float* __restrict__ bvp) {
    int tile = blockIdx.x;
    const float* W; const float* bias; float* C; int N; int n0;
    if (tile < 6)       { W = Wq;  bias = 0;   C = g_q;  N = CS;    n0 = tile*64; }
    else if (tile < 12) { W = Wk;  bias = 0;   C = g_k;  N = CS;    n0 = (tile-6)*64; }
    else if (tile < 18) { W = Wv;  bias = 0;   C = g_v;  N = CS;    n0 = (tile-12)*64; }
    else if (tile < 21) { W = Wqp; bias = bqp; C = g_qp; N = NQP*3; n0 = (tile-18)*64; }
    else if (tile < 24) { W = Wkp; bias = bkp; C = g_kp; N = NQP*3; n0 = (tile-21)*64; }
    else                { W = Wvp; bias = bvp; C = g_vp; N = NVP*3; n0 = (tile-24)*64; }

    __shared__ float As[2][16][68], Bs[2][16][68];
    int t = threadIdx.x, tx = t & 15, ty = t >> 4;
    int m0 = blockIdx.y * 64;
    int arow = t >> 2, akq = (t & 3) * 4;
    float acc[4][4] = {};
    float4 ra, rb;

    // prologue: load k0=0
    ra = *(const float4*)&g_s[(m0 + arow)*CS + akq];
    {
        int col = n0 + tx*4;
        if (col + 3 < N) rb = *(const float4*)&W[(size_t)ty*N + col];
        else {
            rb.x = (col   < N) ? W[(size_t)ty*N + col  ] : 0.f;
            rb.y = (col+1 < N) ? W[(size_t)ty*N + col+1] : 0.f;
            rb.z = (col+2 < N) ? W[(size_t)ty*N + col+2] : 0.f;
            rb.w = (col+3 < N) ? W[(size_t)ty*N + col+3] : 0.f;
        }
    }
    As[0][akq+0][arow] = ra.x; As[0][akq+1][arow] = ra.y;
    As[0][akq+2][arow] = ra.z; As[0][akq+3][arow] = ra.w;
    *(float4*)&Bs[0][ty][tx*4] = rb;
    __syncthreads();

    const int NIT = CS/16;   // 24
    for (int it = 0; it < NIT; it++) {
        int b = it & 1;
        if (it + 1 < NIT) {
            int k0 = (it + 1) * 16;
            ra = *(const float4*)&g_s[(m0 + arow)*CS + k0 + akq];
            int col = n0 + tx*4;
            if (col + 3 < N) rb = *(const float4*)&W[(size_t)(k0 + ty)*N + col];
            else {
                rb.x = (col   < N) ? W[(size_t)(k0+ty)*N + col  ] : 0.f;
                rb.y = (col+1 < N) ? W[(size_t)(k0+ty)*N + col+1] : 0.f;
                rb.z = (col+2 < N) ? W[(size_t)(k0+ty)*N + col+2] : 0.f;
                rb.w = (col+3 < N) ? W[(size_t)(k0+ty)*N + col+3] : 0.f;
            }
        }
        #pragma unroll
        for (int k = 0; k < 16; k++) {
            float4 a = *(const float4*)&As[b][k][ty*4];
            float4 bb = *(const float4*)&Bs[b][k][tx*4];
            acc[0][0] += a.x*bb.x; acc[0][1] += a.x*bb.y; acc[0][2] += a.x*bb.z; acc[0][3] += a.x*bb.w;
            acc[1][0] += a.y*bb.x; acc[1][1] += a.y*bb.y; acc[1][2] += a.y*bb.z; acc[1][3] += a.y*bb.w;
            acc[2][0] += a.z*bb.x; acc[2][1] += a.z*bb.y; acc[2][2] += a.z*bb.z; acc[2][3] += a.z*bb.w;
            acc[3][0] += a.w*bb.x; acc[3][1] += a.w*bb.y; acc[3][2] += a.w*bb.z; acc[3][3] += a.w*bb.w;
        }
        if (it + 1 < NIT) {
            int nb = (it + 1) & 1;
            As[nb][akq+0][arow] = ra.x; As[nb][akq+1][arow] = ra.y;
            As[nb][akq+2][arow] = ra.z; As[nb][akq+3][arow] = ra.w;
            *(float4*)&Bs[nb][ty][tx*4] = rb;
            __syncthreads();
        }
    }
    #pragma unroll
    for (int mi = 0; mi < 4; mi++) {
        int row = m0 + ty*4 + mi;
        #pragma unroll
        for (int ni = 0; ni < 4; ni++) {
            int col = n0 + tx*4 + ni;
            if (col < N) C[(size_t)row*N + col] = acc[mi][ni] + (bias ? bias[col] : 0.f);
        }
    }
}

// ---------------- frames for V points only ----------------
__global__ void k_framesV(const float* __restrict__ rots, const float* __restrict__ trans) {
    int idx = blockIdx.x * blockDim.x + threadIdx.x;
    if (idx >= L * NVP) return;
    int l = idx / NVP;
    const float* R = rots + l*9;
    const float* p = g_vp + (size_t)idx*3;
    float x = p[0], y = p[1], z = p[2];
    float* o = g_vg + (size_t)idx*3;
    o[0] = R[0]*x + R[1]*y + R[2]*z + trans[l*3 + 0];
    o[1] = R[3]*x + R[4]*y + R[5]*z + trans[l*3 + 1];
    o[2] = R[6]*x + R[7]*y + R[8]*z + trans[l*3 + 2];
}

// ---------------- pack q/k into 48-dim logit vectors ----------------
__global__ void k_pack(const float* __restrict__ rots, const float* __restrict__ trans,
                       const float* __restrict__ hw) {
    int idx = blockIdx.x * blockDim.x + threadIdx.x;
    if (idx >= L*H) return;
    int l = idx / H, h = idx % H;
    float R[9];
    #pragma unroll
    for (int i = 0; i < 9; i++) R[i] = rots[l*9 + i];
    float t0 = trans[l*3 + 0], t1 = trans[l*3 + 1], t2 = trans[l*3 + 2];
    float wc = log1pf(__expf(hw[h]));
    const float sc = 0.17677669529663687f;
    float* qo = g_qpk + (size_t)idx*KP;
    float* ko = g_kpk + (size_t)idx*KP;
    #pragma unroll
    for (int d = 0; d < D; d++) {
        qo[d] = g_q[l*CS + h*D + d] * sc;
        ko[d] = g_k[l*CS + h*D + d];
    }
    float qn = 0.f, kn = 0.f;
    #pragma unroll
    for (int p = 0; p < 4; p++) {
        const float* qp = &g_qp[l*(NQP*3) + h*12 + p*3];
        float x = qp[0], y = qp[1], z = qp[2];
        float gx = R[0]*x + R[1]*y + R[2]*z + t0;
        float gy = R[3]*x + R[4]*y + R[5]*z + t1;
        float gz = R[6]*x + R[7]*y + R[8]*z + t2;
        qn += gx*gx + gy*gy + gz*gz;
        qo[32 + p*3 + 0] = wc*gx; qo[32 + p*3 + 1] = wc*gy; qo[32 + p*3 + 2] = wc*gz;
        const float* kp = &g_kp[l*(NQP*3) + h*12 + p*3];
        x = kp[0]; y = kp[1]; z = kp[2];
        gx = R[0]*x + R[1]*y + R[2]*z + t0;
        gy = R[3]*x + R[4]*y + R[5]*z + t1;
        gz = R[6]*x + R[7]*y + R[8]*z + t2;
        kn += gx*gx + gy*gy + gz*gz;
        ko[32 + p*3 + 0] = gx; ko[32 + p*3 + 1] = gy; ko[32 + p*3 + 2] = gz;
    }
    qo[44] = -0.5f*wc*qn; qo[45] = 1.f; qo[46] = 0.f; qo[47] = 0.f;
    ko[44] = 1.f; ko[45] = -0.5f*wc*kn; ko[46] = 0.f; ko[47] = 0.f;
}

// ---------------- logits GEMM: [64x48]@[48x64] per (h, tile) ----------------
__global__ __launch_bounds__(256)
void k_logits() {
    int h = blockIdx.z;
    int i0 = blockIdx.y * 64, j0 = blockIdx.x * 64;
    __shared__ float As[KP][68], Bs[KP][68];
    int t = threadIdx.x, tx = t & 15, ty = t >> 4;
    {
        int row = t >> 2, kq = (t & 3) * 4;
        #pragma unroll
        for (int kk = 0; kk < KP; kk += 16) {
            float4 a = *(const float4*)&g_qpk[((size_t)(i0 + row)*H + h)*KP + kk + kq];
            As[kk+kq+0][row] = a.x; As[kk+kq+1][row] = a.y;
            As[kk+kq+2][row] = a.z; As[kk+kq+3][row] = a.w;
            float4 b = *(const float4*)&g_kpk[((size_t)(j0 + row)*H + h)*KP + kk + kq];
            Bs[kk+kq+0][row] = b.x; Bs[kk+kq+1][row] = b.y;
            Bs[kk+kq+2][row] = b.z; Bs[kk+kq+3][row] = b.w;
        }
    }
    __syncthreads();
    float acc[4][4] = {};
    #pragma unroll
    for (int k = 0; k < KP; k++) {
        float4 a = *(const float4*)&As[k][ty*4];
        float4 b = *(const float4*)&Bs[k][tx*4];
        acc[0][0] += a.x*b.x; acc[0][1] += a.x*b.y; acc[0][2] += a.x*b.z; acc[0][3] += a.x*b.w;
        acc[1][0] += a.y*b.x; acc[1][1] += a.y*b.y; acc[1][2] += a.y*b.z; acc[1][3] += a.y*b.w;
        acc[2][0] += a.z*b.x; acc[2][1] += a.z*b.y; acc[2][2] += a.z*b.z; acc[2][3] += a.z*b.w;
        acc[3][0] += a.w*b.x; acc[3][1] += a.w*b.y; acc[3][2] += a.w*b.z; acc[3][3] += a.w*b.w;
    }
    #pragma unroll
    for (int mi = 0; mi < 4; mi++) {
        float4 v = make_float4(acc[mi][0], acc[mi][1], acc[mi][2], acc[mi][3]);
        *(float4*)&g_attn[(size_t)h*LL + (size_t)(i0 + ty*4 + mi)*L + j0 + tx*4] = v;
    }
}

// ---------------- fused pair-bias + logit-add + softmax (256 threads) ----------------
#define CT 8
__global__ __launch_bounds__(256)
void k_biassm(const float* __restrict__ pair, const float* __restrict__ Wpb) {
    int i = blockIdx.x, t = threadIdx.x;
    __shared__ float pj[CT][768];       // 24.6 KB
    __shared__ float wsh[CZ*H];         // 6 KB
    __shared__ float red8[H][8];
    __shared__ float sred[H];
    for (int x = t; x < CZ*H; x += 256) wsh[x] = Wpb[x];
    const float* prow = pair + (size_t)i * L * CZ;
    float acc[3][12] = {};
    int c4 = (t & 1) * 4, jb = t >> 1;     // jb in 0..127
    float4 pv[6];

    // prologue chunk 0
    #pragma unroll
    for (int p = 0; p < 6; p++)
        pv[p] = *(const float4*)&prow[(size_t)(jb + 128*p)*CZ + c4];
    #pragma unroll
    for (int p = 0; p < 6; p++) {
        int j = jb + 128*p;
        pj[c4+0][j] = pv[p].x; pj[c4+1][j] = pv[p].y;
        pj[c4+2][j] = pv[p].z; pj[c4+3][j] = pv[p].w;
    }
    __syncthreads();

    const int NCH = CZ / CT;   // 16
    for (int it = 0; it < NCH; it++) {
        if (it + 1 < NCH) {
            int c0 = (it + 1) * CT;
            #pragma unroll
            for (int p = 0; p < 6; p++)
                pv[p] = *(const float4*)&prow[(size_t)(jb + 128*p)*CZ + c0 + c4];
        }
        int cb = it * CT;
        #pragma unroll
        for (int ck = 0; ck < CT; ck++) {
            float wv[12];
            #pragma unroll
            for (int h = 0; h < 12; h++) wv[h] = wsh[(cb + ck)*12 + h];
            #pragma unroll
            for (int r = 0; r < 3; r++) {
                float a = pj[ck][t + 256*r];
                #pragma unroll
                for (int h = 0; h < 12; h++) acc[r][h] += a * wv[h];
            }
        }
        if (it + 1 < NCH) {
            __syncthreads();
            #pragma unroll
            for (int p = 0; p < 6; p++) {
                int j = jb + 128*p;
                pj[c4+0][j] = pv[p].x; pj[c4+1][j] = pv[p].y;
                pj[c4+2][j] = pv[p].z; pj[c4+3][j] = pv[p].w;
            }
            __syncthreads();
        }
    }

    // add precomputed logits
    #pragma unroll
    for (int h = 0; h < 12; h++)
        #pragma unroll
        for (int r = 0; r < 3; r++)
            acc[r][h] += g_attn[(size_t)h*LL + (size_t)i*L + t + 256*r];

    int w = t >> 5, lane = t & 31;
    // ---- max reduce ----
    #pragma unroll
    for (int h = 0; h < 12; h++) {
        float m = fmaxf(acc[0][h], fmaxf(acc[1][h], acc[2][h]));
        #pragma unroll
        for (int o = 16; o; o >>= 1) m = fmaxf(m, __shfl_xor_sync(0xffffffffu, m, o));
        if (lane == 0) red8[h][w] = m;
    }
    __syncthreads();
    for (int h = w; h < 12; h += 8) {
        float m = (lane < 8) ? red8[h][lane] : -3.0e38f;
        m = fmaxf(m, __shfl_xor_sync(0xffffffffu, m, 4));
        m = fmaxf(m, __shfl_xor_sync(0xffffffffu, m, 2));
        m = fmaxf(m, __shfl_xor_sync(0xffffffffu, m, 1));
        if (lane == 0) sred[h] = m;
    }
    __syncthreads();
    float mh[12];
    #pragma unroll
    for (int h = 0; h < 12; h++) mh[h] = sred[h];
    __syncthreads();
    // ---- exp + sum reduce ----
    #pragma unroll
    for (int h = 0; h < 12; h++) {
        float s = 0.f;
        #pragma unroll
        for (int r = 0; r < 3; r++) {
            acc[r][h] = __expf(acc[r][h] - mh[h]);
            s += acc[r][h];
        }
        #pragma unroll
        for (int o = 16; o; o >>= 1) s += __shfl_xor_sync(0xffffffffu, s, o);
        if (lane == 0) red8[h][w] = s;
    }
    __syncthreads();
    for (int h = w; h < 12; h += 8) {
        float s = (lane < 8) ? red8[h][lane] : 0.f;
        s += __shfl_xor_sync(0xffffffffu, s, 4);
        s += __shfl_xor_sync(0xffffffffu, s, 2);
        s += __shfl_xor_sync(0xffffffffu, s, 1);
        if (lane == 0) sred[h] = s;
    }
    __syncthreads();
    #pragma unroll
    for (int h = 0; h < 12; h++) {
        float inv = 1.f / sred[h];
        #pragma unroll
        for (int r = 0; r < 3; r++)
            g_attn[(size_t)h*LL + (size_t)i*L + t + 256*r] = acc[r][h] * inv;
    }
}

// ---------------- fused AV (56 features), pipelined ----------------
__global__ __launch_bounds__(256)
void k_avf() {
    int h = blockIdx.y, i0 = blockIdx.x * 64;
    __shared__ float As[2][32][68];    // [j][i]
    __shared__ float Bs[2][32][64];    // [j][f]
    int t = threadIdx.x, tx = t & 15, ty = t >> 4;
    int aii = t >> 3, aj4 = (t & 7) * 4;
    int bj = t >> 3, bg = t & 7;
    // zero the constant-zero tail f=56..63 once per buffer
    Bs[0][t >> 3][56 + (t & 7)] = 0.f;
    Bs[1][t >> 3][56 + (t & 7)] = 0.f;

    float4 ra0, ra1, rv0, rv1;
    auto ldA = [&](int j0) {
        ra0 = *(const float4*)&g_attn[(size_t)h*LL + (size_t)(i0 + aii)*L + j0 + aj4];
        ra1 = *(const float4*)&g_attn[(size_t)h*LL + (size_t)(i0 + aii + 32)*L + j0 + aj4];
    };
    auto ldB = [&](int j0) {
        if (bg < 4) {
            rv0 = *(const float4*)&g_v[(size_t)(j0 + bj)*CS + h*D + bg*8];
            rv1 = *(const float4*)&g_v[(size_t)(j0 + bj)*CS + h*D + bg*8 + 4];
        } else if (bg < 7) {
            int off = (bg - 4) * 8;
            rv0 = *(const float4*)&g_vg[(size_t)(j0 + bj)*(NVP*3) + h*24 + off];
            rv1 = *(const float4*)&g_vg[(size_t)(j0 + bj)*(NVP*3) + h*24 + off + 4];
        }
    };
    auto stAB = [&](int b) {
        As[b][aj4+0][aii]      = ra0.x; As[b][aj4+1][aii]      = ra0.y;
        As[b][aj4+2][aii]      = ra0.z; As[b][aj4+3][aii]      = ra0.w;
        As[b][aj4+0][aii + 32] = ra1.x; As[b][aj4+1][aii + 32] = ra1.y;
        As[b][aj4+2][aii + 32] = ra1.z; As[b][aj4+3][aii + 32] = ra1.w;
        if (bg < 7) {
            *(float4*)&Bs[b][bj][bg*8]     = rv0;
            *(float4*)&Bs[b][bj][bg*8 + 4] = rv1;
        }
    };

    float acc[4][4] = {};
    ldA(0); ldB(0); stAB(0);
    __syncthreads();
    const int NIT = L / 32;  // 24
    for (int it = 0; it < NIT; it++) {
        int b = it & 1;
        if (it + 1 < NIT) { ldA((it+1)*32); ldB((it+1)*32); }
        #pragma unroll
        for (int j = 0; j < 32; j++) {
            float4 a = *(const float4*)&As[b][j][ty*4];
            float4 v = *(const float4*)&Bs[b][j][tx*4];
            acc[0][0] += a.x*v.x; acc[0][1] += a.x*v.y; acc[0][2] += a.x*v.z; acc[0][3] += a.x*v.w;
            acc[1][0] += a.y*v.x; acc[1][1] += a.y*v.y; acc[1][2] += a.y*v.z; acc[1][3] += a.y*v.w;
            acc[2][0] += a.z*v.x; acc[2][1] += a.z*v.y; acc[2][2] += a.z*v.z; acc[2][3] += a.z*v.w;
            acc[3][0] += a.w*v.x; acc[3][1] += a.w*v.y; acc[3][2] += a.w*v.z; acc[3][3] += a.w*v.w;
        }
        if (it + 1 < NIT) {
            stAB((it + 1) & 1);
            __syncthreads();
        }
    }
    #pragma unroll
    for (int mi = 0; mi < 4; mi++) {
        int ii = i0 + ty*4 + mi;
        #pragma unroll
        for (int ni = 0; ni < 4; ni++) {
            int f = tx*4 + ni;
            if (f < 32)      g_cat[(size_t)ii*OUTD + h*D + f] = acc[mi][ni];
            else if (f < 56) g_optg[(size_t)ii*(NVP*3) + h*24 + f - 32] = acc[mi][ni];
        }
    }
}

// ---------------- invert frames on output points ----------------
__global__ void k_ptsl(const float* __restrict__ rots, const float* __restrict__ trans) {
    int idx = blockIdx.x * blockDim.x + threadIdx.x;
    if (idx >= L * NVP) return;
    int l = idx / NVP, n = idx % NVP;
    const float* R = rots + l*9;
    float x = g_optg[(size_t)idx*3 + 0] - trans[l*3 + 0];
    float y = g_optg[(size_t)idx*3 + 1] - trans[l*3 + 1];
    float z = g_optg[(size_t)idx*3 + 2] - trans[l*3 + 2];
    g_cat[(size_t)l*OUTD + CS + n*3 + 0] = R[0]*x + R[3]*y + R[6]*z;
    g_cat[(size_t)l*OUTD + CS + n*3 + 1] = R[1]*x + R[4]*y + R[7]*z;
    g_cat[(size_t)l*OUTD + CS + n*3 + 2] = R[2]*x + R[5]*y + R[8]*z;
}

// ---------------- out_pair: block = one i ----------------
__global__ __launch_bounds__(256)
void k_opair(const float* __restrict__ pair) {
    int i = blockIdx.x, t = threadIdx.x, w = t >> 5, lane = t & 31;
    __shared__ float asr[H*L];     // 36 KB
    for (int x = t; x < H*L; x += 256)
        asr[x] = g_attn[(size_t)(x / L)*LL + (size_t)i*L + (x % L)];
    __syncthreads();
    float4 acc[12];
    #pragma unroll
    for (int h = 0; h < 12; h++) acc[h] = make_float4(0.f, 0.f, 0.f, 0.f);
    const float4* pr = (const float4*)(pair + (size_t)i * L * CZ);
    int jbeg = w*96, jend = jbeg + 96;
    for (int j = jbeg; j < jend; j += 2) {
        float4 p0 = pr[(size_t)j*32 + lane];
        float4 p1 = pr[(size_t)(j+1)*32 + lane];
        float2 a[12];
        #pragma unroll
        for (int h = 0; h < 12; h++) a[h] = *(const float2*)&asr[h*L + j];
        #pragma unroll
        for (int h = 0; h < 12; h++) {
            acc[h].x += a[h].x*p0.x + a[h].y*p1.x;
            acc[h].y += a[h].x*p0.y + a[h].y*p1.y;
            acc[h].z += a[h].x*p0.z + a[h].y*p1.z;
            acc[h].w += a[h].x*p0.w + a[h].y*p1.w;
        }
    }
    for (int half = 4; half >= 1; half >>= 1) {
        __syncthreads();
        if (w >= half && w < 2*half) {
            #pragma unroll
            for (int h = 0; h < 12; h++)
                *(float4*)&asr[(w - half)*1536 + h*128 + lane*4] = acc[h];
        }
        __syncthreads();
        if (w < half) {
            #pragma unroll
            for (int h = 0; h < 12; h++) {
                float4 v = *(const float4*)&asr[w*1536 + h*128 + lane*4];
                acc[h].x += v.x; acc[h].y += v.y; acc[h].z += v.z; acc[h].w += v.w;
            }
        }
    }
    if (w == 0) {
        #pragma unroll
        for (int h = 0; h < 12; h++)
            *(float4*)&g_cat[(size_t)i*OUTD + CS + NVP*3 + h*128 + lane*4] = acc[h];
    }
}

// ---------------- final GEMM, split-K partials, pipelined ----------------
__global__ __launch_bounds__(256)
void k_fpart(const float* __restrict__ Wo) {
    int n0 = blockIdx.x * 64, m0 = blockIdx.y * 64, kz = blockIdx.z;
    __shared__ float As[2][16][68], Bs[2][16][68];
    int t = threadIdx.x, tx = t & 15, ty = t >> 4;
    int arow = t >> 2, akq = (t & 3) * 4;
    float acc[4][4] = {};
    int kbeg = kz * (OUTD / KSPLIT);
    const int NIT = (OUTD / KSPLIT) / 16;   // 23
    float4 ra, rb;

    ra = *(const float4*)&g_cat[(size_t)(m0 + arow)*OUTD + kbeg + akq];
    rb = *(const float4*)&Wo[(size_t)(kbeg + ty)*CS + n0 + tx*4];
    As[0][akq+0][arow] = ra.x; As[0][akq+1][arow] = ra.y;
    As[0][akq+2][arow] = ra.z; As[0][akq+3][arow] = ra.w;
    *(float4*)&Bs[0][ty][tx*4] = rb;
    __syncthreads();

    for (int it = 0; it < NIT; it++) {
        int b = it & 1;
        if (it + 1 < NIT) {
            int k0 = kbeg + (it + 1) * 16;
            ra = *(const float4*)&g_cat[(size_t)(m0 + arow)*OUTD + k0 + akq];
            rb = *(const float4*)&Wo[(size_t)(k0 + ty)*CS + n0 + tx*4];
        }
        #pragma unroll
        for (int k = 0; k < 16; k++) {
            float4 a = *(const float4*)&As[b][k][ty*4];
            float4 bb = *(const float4*)&Bs[b][k][tx*4];
            acc[0][0] += a.x*bb.x; acc[0][1] += a.x*bb.y; acc[0][2] += a.x*bb.z; acc[0][3] += a.x*bb.w;
            acc[1][0] += a.y*bb.x; acc[1][1] += a.y*bb.y; acc[1][2] += a.y*bb.z; acc[1][3] += a.y*bb.w;
            acc[2][0] += a.z*bb.x; acc[2][1] += a.z*bb.y; acc[2][2] += a.z*bb.z; acc[2][3] += a.z*bb.w;
            acc[3][0] += a.w*bb.x; acc[3][1] += a.w*bb.y; acc[3][2] += a.w*bb.z; acc[3][3] += a.w*bb.w;
        }
        if (it + 1 < NIT) {
            int nb = (it + 1) & 1;
            As[nb][akq+0][arow] = ra.x; As[nb][akq+1][arow] = ra.y;
            As[nb][akq+2][arow] = ra.z; As[nb][akq+3][arow] = ra.w;
            *(float4*)&Bs[nb][ty][tx*4] = rb;
            __syncthreads();
        }
    }
    #pragma unroll
    for (int mi = 0; mi < 4; mi++) {
        float4 v = make_float4(acc[mi][0], acc[mi][1], acc[mi][2], acc[mi][3]);
        *(float4*)&g_fpart[kz][(size_t)(m0 + ty*4 + mi)*CS + n0 + tx*4] = v;
    }
}

__global__ void k_fred(const float* __restrict__ bo, float* __restrict__ out) {
    int x = blockIdx.x * 256 + threadIdx.x;
    if (x >= L*CS) return;
    float s = bo[x % CS];
    #pragma unroll
    for (int p = 0; p < KSPLIT; p++) s += g_fpart[p][x];
    out[x] = s;
}

// ---------------- launch ----------------
extern "C" void kernel_launch(void* const* d_in, const int* in_sizes, int n_in,
                              void* d_out, int out_size) {
    const float* single = (const float*)d_in[0];
    const float* pair   = (const float*)d_in[1];
    const float* rots   = (const float*)d_in[2];
    const float* trans  = (const float*)d_in[3];
    const float* ln_g   = (const float*)d_in[4];
    const float* ln_b   = (const float*)d_in[5];
    const float* Wq     = (const float*)d_in[6];
    const float* Wk     = (const float*)d_in[7];
    const float* Wv     = (const float*)d_in[8];
    const float* Wqp    = (const float*)d_in[9];
    const float* bqp    = (const float*)d_in[10];
    const float* Wkp    = (const float*)d_in[11];
    const float* bkp    = (const float*)d_in[12];
    const float* Wvp    = (const float*)d_in[13];
    const float* bvp    = (const float*)d_in[14];
    const float* Wpb    = (const float*)d_in[15];
    const float* hw     = (const float*)d_in[16];
    const float* Wo     = (const float*)d_in[17];
    const float* bo     = (const float*)d_in[18];
    float* out = (float*)d_out;

    k_ln<<<L, CS>>>(single, ln_g, ln_b);
    k_projall<<<dim3(29, 12), 256>>>(Wq, Wk, Wv, Wqp, bqp, Wkp, bkp, Wvp, bvp);

    k_framesV<<<(L*NVP + 255)/256, 256>>>(rots, trans);
    k_pack<<<(L*H + 255)/256, 256>>>(rots, trans, hw);

    k_logits<<<dim3(12, 12, H), 256>>>();
    k_biassm<<<L, 256>>>(pair, Wpb);

    k_avf<<<dim3(12, H), 256>>>();
    k_ptsl<<<(L*NVP + 255)/256, 256>>>(rots, trans);
    k_opair<<<L, 256>>>(pair);

    k_fpart<<<dim3(6, 12, KSPLIT), 256>>>(Wo);
    k_fred<<<(L*CS + 255)/256, 256>>>(bo, out);
}